// round 2
// baseline (speedup 1.0000x reference)
#include <cuda_runtime.h>

// Analytic reduction of the "quantum multi-head attention" reference:
// For each contiguous group of D_K=8 floats (one head):
//   phi_i = x_i + theta_i,  c_i = cos(phi_i)
//   out[j] = prod_{i=0..j} c_i      (j = 1..7)
//   out[0] = prod_{i=1..7} c_i
// (CNOT chain permutes basis states; <Z_j> = product of cos(phi_i) over the
// XOR support of final bit j; bits independent Bernoulli.)
//
// |phi| <= |x| + |theta| ~ 7 for N(0,1) inputs, so __cosf (MUFU fast path,
// abs err ~1e-6 in this range) is far inside the 1e-3 rel-err budget.

__global__ __launch_bounds__(256)
void quantum_heads_kernel(const float* __restrict__ x,
                          const float* __restrict__ theta,
                          float* __restrict__ out,
                          int ngroups)
{
    int g = blockIdx.x * blockDim.x + threadIdx.x;
    if (g >= ngroups) return;

    // theta: 8 floats, two vector loads (broadcast, L1/L2 hot)
    const float4* tp = reinterpret_cast<const float4*>(theta);
    float4 t0 = __ldg(tp + 0);
    float4 t1 = __ldg(tp + 1);

    const float4* xp = reinterpret_cast<const float4*>(x) + (size_t)g * 2;
    float4 a = __ldg(xp + 0);
    float4 b = __ldg(xp + 1);

    float c0 = __cosf(a.x + t0.x);
    float c1 = __cosf(a.y + t0.y);
    float c2 = __cosf(a.z + t0.z);
    float c3 = __cosf(a.w + t0.w);
    float c4 = __cosf(b.x + t1.x);
    float c5 = __cosf(b.y + t1.y);
    float c6 = __cosf(b.z + t1.z);
    float c7 = __cosf(b.w + t1.w);

    // prefix products p_j = c0*...*cj
    float p1 = c0 * c1;
    float p2 = p1 * c2;
    float p3 = p2 * c3;
    float p4 = p3 * c4;
    float p5 = p4 * c5;
    float p6 = p5 * c6;
    float p7 = p6 * c7;
    // out[0] = c1*...*c7 (suffix product; avoid dividing by possibly-zero c0)
    float s = ((c1 * c2) * (c3 * c4)) * ((c5 * c6) * c7);

    float4* op = reinterpret_cast<float4*>(out) + (size_t)g * 2;
    op[0] = make_float4(s,  p1, p2, p3);
    op[1] = make_float4(p4, p5, p6, p7);
}

extern "C" void kernel_launch(void* const* d_in, const int* in_sizes, int n_in,
                              void* d_out, int out_size)
{
    const float* x     = (const float*)d_in[0];
    const float* theta = (const float*)d_in[1];
    float* out         = (float*)d_out;

    int ngroups = in_sizes[0] / 8;   // one group = 8 contiguous floats (one head)
    int threads = 256;
    int blocks  = (ngroups + threads - 1) / threads;
    quantum_heads_kernel<<<blocks, threads>>>(x, theta, out, ngroups);
}

// round 3
// speedup vs baseline: 1.0047x; 1.0047x over previous
#include <cuda_runtime.h>

// Analytic reduction (see prior rounds): per 8-float group,
//   c_i = cos(x_i + theta_i)
//   out[j] = prod_{i=0..j} c_i   (j=1..7),   out[0] = prod_{i=1..7} c_i
//
// This version splits each group across TWO threads (one float4 each) and
// exchanges the 4-way cosine product with the pair partner via shfl_xor,
// doubling occupancy and halving the per-thread serial MUFU chain.
//
// |phi| <~ 7 so __cosf (MUFU fast path) is ~1e-6 abs err, far under 1e-3.

__global__ __launch_bounds__(256)
void quantum_heads_kernel(const float* __restrict__ x,
                          const float* __restrict__ theta,
                          float* __restrict__ out,
                          int nquads)   // nquads = 2 * ngroups
{
    int tid = blockIdx.x * blockDim.x + threadIdx.x;
    if (tid >= nquads) return;

    int half = tid & 1;   // 0 = first 4 lanes of group, 1 = last 4

    // theta quad for this half (broadcast, L1-hot)
    const float4* tp = reinterpret_cast<const float4*>(theta);
    float4 t = __ldg(tp + half);

    const float4* xp = reinterpret_cast<const float4*>(x);
    float4 v = __ldg(xp + tid);

    float c0 = __cosf(v.x + t.x);
    float c1 = __cosf(v.y + t.y);
    float c2 = __cosf(v.z + t.z);
    float c3 = __cosf(v.w + t.w);

    float p01  = c0 * c1;
    float p012 = p01 * c2;
    float full = p012 * c3;          // product of this thread's 4 cosines

    // exchange full products with pair partner (lanes 2g, 2g+1 adjacent)
    float other = __shfl_xor_sync(0xFFFFFFFFu, full, 1);

    float4 o;
    if (half == 0) {
        // outputs 0..3:  out0 = c1*c2*c3 * (c4..c7),  out1..3 = prefixes
        o.x = (c1 * c2) * (c3 * other);
        o.y = p01;
        o.z = p012;
        o.w = full;
    } else {
        // outputs 4..7: prefix products continued with P3 = c0..c3 from partner
        o.x = other * c0;
        o.y = other * p01;
        o.z = other * p012;
        o.w = other * full;
    }

    float4* op = reinterpret_cast<float4*>(out);
    op[tid] = o;
}

extern "C" void kernel_launch(void* const* d_in, const int* in_sizes, int n_in,
                              void* d_out, int out_size)
{
    const float* x     = (const float*)d_in[0];
    const float* theta = (const float*)d_in[1];
    float* out         = (float*)d_out;

    int nquads  = in_sizes[0] / 4;   // one thread per float4 (half group)
    int threads = 256;
    int blocks  = (nquads + threads - 1) / threads;
    quantum_heads_kernel<<<blocks, threads>>>(x, theta, out, nquads);
}

// round 4
// speedup vs baseline: 1.0537x; 1.0488x over previous
#include <cuda_runtime.h>

// Analytic reduction (see prior rounds): per 8-float group,
//   c_i = cos(x_i + theta_i)
//   out[j] = prod_{i=0..j} c_i   (j=1..7),   out[0] = prod_{i=1..7} c_i
//
// One thread per float4 (half group); pair partners exchange their 4-way
// cosine product via shfl_xor. Kernel is launch-overhead bound (all pipes
// <6% in ncu), so this round minimizes launch shape: grid=128, block=1024,
// <=1 CTA/SM, one flat wave.

__global__ __launch_bounds__(1024)
void quantum_heads_kernel(const float* __restrict__ x,
                          const float* __restrict__ theta,
                          float* __restrict__ out,
                          int nquads)   // nquads = 2 * ngroups
{
    int tid = blockIdx.x * blockDim.x + threadIdx.x;
    if (tid >= nquads) return;

    int half = tid & 1;   // 0 = first 4 lanes of group, 1 = last 4

    const float4* tp = reinterpret_cast<const float4*>(theta);
    float4 t = __ldg(tp + half);

    const float4* xp = reinterpret_cast<const float4*>(x);
    float4 v = __ldg(xp + tid);

    float c0 = __cosf(v.x + t.x);
    float c1 = __cosf(v.y + t.y);
    float c2 = __cosf(v.z + t.z);
    float c3 = __cosf(v.w + t.w);

    float p01  = c0 * c1;
    float p012 = p01 * c2;
    float full = p012 * c3;          // product of this thread's 4 cosines

    // exchange 4-way products with pair partner (lanes 2g, 2g+1 adjacent)
    float other = __shfl_xor_sync(0xFFFFFFFFu, full, 1);

    float4 o;
    if (half == 0) {
        // outputs 0..3:  out0 = c1*c2*c3 * (c4..c7),  then prefixes
        o.x = (c1 * c2) * (c3 * other);
        o.y = p01;
        o.z = p012;
        o.w = full;
    } else {
        // outputs 4..7: prefixes continued with P3 = c0..c3 from partner
        o.x = other * c0;
        o.y = other * p01;
        o.z = other * p012;
        o.w = other * full;
    }

    reinterpret_cast<float4*>(out)[tid] = o;
}

extern "C" void kernel_launch(void* const* d_in, const int* in_sizes, int n_in,
                              void* d_out, int out_size)
{
    const float* x     = (const float*)d_in[0];
    const float* theta = (const float*)d_in[1];
    float* out         = (float*)d_out;

    int nquads  = in_sizes[0] / 4;   // one thread per float4 (half group)
    int threads = 1024;
    int blocks  = (nquads + threads - 1) / threads;   // 128 for the bench shape
    quantum_heads_kernel<<<blocks, threads>>>(x, theta, out, nquads);
}